// round 15
// baseline (speedup 1.0000x reference)
#include <cuda_runtime.h>

#define B_ 4
#define C_ 64
#define N_ 8192
#define K_ 32
#define R2_ 0.04f
#define BN_EPS_ 1e-5f
#define NC 5
#define NCELL (NC * NC * NC)
#define INFB 0x7f800000u

typedef unsigned long long ull;

#define FMA2ACC(acc, a, bb) asm("fma.rn.f32x2 %0, %1, %2, %0;" : "+l"(acc) : "l"(a), "l"(bb))

__device__ __forceinline__ ull pack2(float lo, float hi) {
    ull r; asm("mov.b64 %0, {%1, %2};" : "=l"(r) : "f"(lo), "f"(hi)); return r;
}
__device__ __forceinline__ void unpack2(ull v, float& lo, float& hi) {
    asm("mov.b64 {%0, %1}, %2;" : "=f"(lo), "=f"(hi) : "l"(v));
}
__device__ __forceinline__ int cell_clamp(float v) {
    int c = (int)(v * 5.0f);
    return min(NC - 1, max(0, c));
}

// Scratch (static __device__ arrays — no allocation)
__device__ float  g_F[B_ * N_ * C_];      // F[b][n][d] = fea row . W_fea[d] * scale
__device__ int    g_gidx[B_ * N_ * K_];   // final (masked) neighbor indices
__device__ ull    g_WsT2[32 * 64];        // packed (w[2c],w[2c+1]) per d, BN-scaled
__device__ float  g_Wc[3 * 64];           // coord weights * scale
__device__ float  g_bias[64];             // BN-folded bias
// grid structures
__device__ int    g_cnt[B_ * NCELL];      // zeroed by agg (last kernel) for replay
__device__ int    g_cellStart[B_ * (NCELL + 1)];
__device__ int    g_rank[B_ * N_];        // intra-cell rank per point
__device__ float4 g_pts[B_ * N_];         // cell-sorted (x,y,z,sq)
__device__ int    g_pid[B_ * N_];         // original point index

// ---------------------------------------------------------------------------
// K1: W-fold block [0] + grid count blocks [1,129). Two-level count: local
// rank via shared atomics, one aggregated global atomicAdd per non-empty
// cell per block. Intra-cell order nondeterministic — covered by the
// order-invariant (d_bits, idx) selection key in knn.
// ---------------------------------------------------------------------------
__global__ __launch_bounds__(256) void k_prep(
    const float* __restrict__ coor,
    const float* __restrict__ W,
    const float* __restrict__ gamma_, const float* __restrict__ beta_,
    const float* __restrict__ rmean, const float* __restrict__ rvar)
{
    const int bid = blockIdx.x;
    const int tid = threadIdx.x;
    if (bid == 0) {
        if (tid < 64) {
            float sc = gamma_[tid] * rsqrtf(rvar[tid] + BN_EPS_);
            g_bias[tid] = beta_[tid] - rmean[tid] * sc;
            g_Wc[tid]       = W[tid * 67 + 64] * sc;
            g_Wc[64 + tid]  = W[tid * 67 + 65] * sc;
            g_Wc[128 + tid] = W[tid * 67 + 66] * sc;
        }
        for (int e = tid; e < 32 * 64; e += 256) {
            int c2 = e >> 6, d = e & 63;
            float sc = gamma_[d] * rsqrtf(rvar[d] + BN_EPS_);
            g_WsT2[e] = pack2(W[d * 67 + 2 * c2] * sc, W[d * 67 + 2 * c2 + 1] * sc);
        }
    } else {
        __shared__ int scnt[NCELL];
        __shared__ int sbase[NCELL];
        for (int i = tid; i < NCELL; i += 256) scnt[i] = 0;
        __syncthreads();

        const int id = (bid - 1) * 256 + tid;
        const int b = id / N_, n = id % N_;     // b uniform per block (32/batch)
        const float* cb = coor + b * 3 * N_;
        int cx = cell_clamp(cb[n]);
        int cy = cell_clamp(cb[N_ + n]);
        int cz = cell_clamp(cb[2 * N_ + n]);
        const int ci = (cz * NC + cy) * NC + cx;
        int lr = atomicAdd(&scnt[ci], 1);
        __syncthreads();

        for (int i = tid; i < NCELL; i += 256) {
            int c = scnt[i];
            if (c) sbase[i] = atomicAdd(&g_cnt[b * NCELL + i], c);
        }
        __syncthreads();
        g_rank[id] = sbase[ci] + lr;
    }
}

// ---------------------------------------------------------------------------
// K2: scatter only (128 blocks, atomic-free via local prefix scan). Small and
// fast — fgemm moved into the knn launch so it overlaps knn instead of
// serializing.
// ---------------------------------------------------------------------------
__global__ __launch_bounds__(256) void scatter_kernel(const float* __restrict__ coor) {
    __shared__ int sPre[NCELL + 1];
    const int bid = blockIdx.x;
    const int tid = threadIdx.x;
    const int b  = bid >> 5;
    const int id = bid * 256 + tid;
    const int n  = id % N_;
    if (tid < 32) {
        int carry = 0;
        if (tid == 0) sPre[0] = 0;
        for (int c0 = 0; c0 < NCELL; c0 += 32) {
            int i = c0 + tid;
            int v = (i < NCELL) ? g_cnt[b * NCELL + i] : 0;
#pragma unroll
            for (int o = 1; o < 32; o <<= 1) {
                int tv = __shfl_up_sync(0xffffffffu, v, o);
                if (tid >= o) v += tv;
            }
            if (i < NCELL) sPre[i + 1] = carry + v;
            carry += __shfl_sync(0xffffffffu, v, 31);
        }
    }
    __syncthreads();
    for (int i = tid; i <= NCELL; i += 256)
        g_cellStart[b * (NCELL + 1) + i] = sPre[i];

    const float* cb = coor + b * 3 * N_;
    float x = cb[n], y = cb[N_ + n], z = cb[2 * N_ + n];
    float sq = fmaf(x, x, fmaf(y, y, z * z));   // same chain as query side
    int cx = cell_clamp(x), cy = cell_clamp(y), cz = cell_clamp(z);
    int pos = sPre[(cz * NC + cy) * NC + cx] + g_rank[id];
    g_pts[b * N_ + pos] = make_float4(x, y, z, sq);
    g_pid[b * N_ + pos] = n;
}

// ---------------------------------------------------------------------------
// K3 (block-fused): blocks [0,1024) = F GEMM (depends only on k_prep — runs
// CONCURRENTLY with knn, filling the memory pipes while knn is issue-bound),
// blocks [1024,5120) = KNN (R11 algorithm, untouched: per-cell prune,
// nearest-cell-first, order-invariant (d_bits,idx) heap, batched fill,
// provable early exit). Shared memory is a union (fgemm 24.8KB / knn 2KB).
// ---------------------------------------------------------------------------
__global__ __launch_bounds__(256) void fgemm_knn(
    const float* __restrict__ coor, const float* __restrict__ fea)
{
    __shared__ __align__(16) char smem_buf[24832];
    const int bid = blockIdx.x;
    const int tid = threadIdx.x;

    if (bid < 1024) {
        // ---- F GEMM: warp = 8 d's x 32 n's, 8 outputs/thread ----
        ull*   s_wt = reinterpret_cast<ull*>(smem_buf);           // [c2][d] 16KB
        float* sfea = reinterpret_cast<float*>(smem_buf + 16384); // [n][c] padded
        const int b   = bid >> 8;            // 256 n-chunks per batch
        const int n0  = (bid & 255) * 32;
        const int w   = tid >> 5, lane = tid & 31;

        for (int e = tid; e < 32 * 64; e += 256) s_wt[e] = g_WsT2[e];
#pragma unroll
        for (int i = 0; i < 8; i++) {
            int c = w * 8 + i;
            sfea[lane * 66 + c] = fea[(b * 64 + c) * N_ + n0 + lane];
        }
        __syncthreads();

        const ull* frow = reinterpret_cast<const ull*>(sfea + lane * 66);
        const int d0 = w * 8;
        ull acc[8];
#pragma unroll
        for (int j = 0; j < 8; j++) acc[j] = 0ull;
#pragma unroll 8
        for (int c2 = 0; c2 < 32; c2++) {
            ull f = frow[c2];
            const ull* wr = s_wt + c2 * 64 + d0;
            ulonglong2 w01 = *reinterpret_cast<const ulonglong2*>(wr);
            ulonglong2 w23 = *reinterpret_cast<const ulonglong2*>(wr + 2);
            ulonglong2 w45 = *reinterpret_cast<const ulonglong2*>(wr + 4);
            ulonglong2 w67 = *reinterpret_cast<const ulonglong2*>(wr + 6);
            FMA2ACC(acc[0], f, w01.x); FMA2ACC(acc[1], f, w01.y);
            FMA2ACC(acc[2], f, w23.x); FMA2ACC(acc[3], f, w23.y);
            FMA2ACC(acc[4], f, w45.x); FMA2ACC(acc[5], f, w45.y);
            FMA2ACC(acc[6], f, w67.x); FMA2ACC(acc[7], f, w67.y);
        }
        float o[8];
#pragma unroll
        for (int j = 0; j < 8; j++) {
            float lo, hi; unpack2(acc[j], lo, hi);
            o[j] = lo + hi;
        }
        float4* dst = reinterpret_cast<float4*>(
            g_F + ((size_t)(b * N_ + n0 + lane)) * 64 + d0);
        dst[0] = make_float4(o[0], o[1], o[2], o[3]);
        dst[1] = make_float4(o[4], o[5], o[6], o[7]);
        return;
    }

    // ---- KNN ----
    ull (*s_stage)[32] = reinterpret_cast<ull(*)[32]>(smem_buf);
    const int kb   = bid - 1024;          // [0,4096)
    const int b    = kb >> 10;
    const int warp = tid >> 5;
    const int lane = tid & 31;
    const int q    = (kb & 1023) * 8 + warp;

    const float* cb = coor + b * 3 * N_;
    const float qx  = cb[q];
    const float qy  = cb[N_ + q];
    const float qz  = cb[2 * N_ + q];
    const float qsq = fmaf(qx, qx, fmaf(qy, qy, qz * qz));

    int s = 0, e = 0;
    unsigned mdu = INFB;
    {
        int qcx = cell_clamp(qx), qcy = cell_clamp(qy), qcz = cell_clamp(qz);
        if (lane < 27) {
            int cx = qcx + (lane % 3) - 1;
            int cy = qcy + ((lane / 3) % 3) - 1;
            int cz = qcz + (lane / 9) - 1;
            if (cx >= 0 && cx < NC && cy >= 0 && cy < NC && cz >= 0 && cz < NC) {
                float bx0 = cx * 0.2f, by0 = cy * 0.2f, bz0 = cz * 0.2f;
                float ddx = fmaxf(0.f, fmaxf(bx0 - qx, qx - (bx0 + 0.2f)));
                float ddy = fmaxf(0.f, fmaxf(by0 - qy, qy - (by0 + 0.2f)));
                float ddz = fmaxf(0.f, fmaxf(bz0 - qz, qz - (bz0 + 0.2f)));
                float md = ddx * ddx + ddy * ddy + ddz * ddz;
                if (md <= R2_ + 1e-5f) {
                    int ci = b * (NCELL + 1) + (cz * NC + cy) * NC + cx;
                    s = g_cellStart[ci];
                    e = g_cellStart[ci + 1];
                    mdu = __float_as_uint(md);
                }
            }
        }
    }

    unsigned mydb  = INFB;
    unsigned myidx = 0u;
    unsigned cmd = INFB, cmi = 0u;
    int maxlane = 0;
    int count = 0;

    const float4* pts = g_pts + b * N_;
    const int*    pid = g_pid + b * N_;

#pragma unroll 1
    for (int r = 0; r < 27; r++) {
        unsigned rmin = __reduce_min_sync(0xffffffffu, mdu);
        if (rmin == INFB) break;
        if (count == 32 &&
            __uint_as_float(cmd) + 4e-6f < __uint_as_float(rmin)) break;
        int j = __ffs(__ballot_sync(0xffffffffu, mdu == rmin)) - 1;
        int cs = __shfl_sync(0xffffffffu, s, j);
        int ce = __shfl_sync(0xffffffffu, e, j);
        if (lane == j) mdu = INFB;

        for (int i0 = cs; i0 < ce; i0 += 32) {
            int i = i0 + lane;
            bool act = i < ce;
            float4 p = act ? pts[i]
                           : make_float4(0.f, 0.f, 0.f, __int_as_float(0x7f800000));
            float dot = fmaf(qx, p.x, fmaf(qy, p.y, qz * p.z));
            float d   = fmaf(-2.f, dot, qsq + p.w);
            d = fmaxf(d, 0.f);
            unsigned db = __float_as_uint(d);
            unsigned pv = act ? (unsigned)pid[i] : 0u;
            bool ok = act && (d <= R2_) &&
                      (db < cmd || (db == cmd && pv < cmi));
            unsigned mask = __ballot_sync(0xffffffffu, ok);

            // ---- batched fill (heap not yet full) ----
            if (count < 32 && mask) {
                int m    = __popc(mask);
                int take = min(32 - count, m);
                int rank = __popc(mask & ((1u << lane) - 1u));
                if (ok && rank < take)
                    s_stage[warp][rank] = ((ull)db << 32) | pv;
                __syncwarp();
                int rr = lane - count;
                if (rr >= 0 && rr < take) {
                    ull v = s_stage[warp][rr];
                    mydb  = (unsigned)(v >> 32);
                    myidx = (unsigned)v;
                }
                count += take;
                if (take == m) mask = 0;
                else
                    for (int t = 0; t < take; t++) mask &= mask - 1;
                if (count == 32) {
                    cmd = __reduce_max_sync(0xffffffffu, mydb);
                    bool eq = (mydb == cmd);
                    cmi = __reduce_max_sync(0xffffffffu, eq ? myidx : 0u);
                    maxlane = __ffs(__ballot_sync(0xffffffffu,
                                        eq && (myidx == cmi))) - 1;
                }
            }

            // ---- eviction (heap full) ----
            while (mask) {
                int jj = __ffs(mask) - 1;
                mask &= mask - 1;
                unsigned djb = __shfl_sync(0xffffffffu, db, jj);
                unsigned cj  = __shfl_sync(0xffffffffu, pv, jj);
                if (djb < cmd || (djb == cmd && cj < cmi)) {
                    if (lane == maxlane) { mydb = djb; myidx = cj; }
                    cmd = __reduce_max_sync(0xffffffffu, mydb);
                    bool eq = (mydb == cmd);
                    cmi = __reduce_max_sync(0xffffffffu, eq ? myidx : 0u);
                    maxlane = __ffs(__ballot_sync(0xffffffffu,
                                        eq && (myidx == cmi))) - 1;
                }
            }
        }
    }
    int finalIdx = (__uint_as_float(mydb) <= R2_) ? (int)myidx : q;
    g_gidx[(b * N_ + q) * K_ + lane] = finalIdx;
}

// ---------------------------------------------------------------------------
// Aggregation: 256 threads = 4 queries x 2 half-warps. Each warp gathers 16
// of its query's 32 F rows (halves the serial LDG->FMA2->max chain; traffic
// unchanged); halves combine via associative max => bit-identical result.
// Block (0,0) re-zeroes g_cnt for the next graph replay.
// ---------------------------------------------------------------------------
__global__ __launch_bounds__(256) void agg_kernel(const float* __restrict__ coor,
                                                  float* __restrict__ out) {
    __shared__ __align__(16) float4 scc[4 * 32];
    __shared__ float spart[2][4][64];
    __shared__ float sout[4 * 64];

    const int b    = blockIdx.y;
    const int q0   = blockIdx.x * 4;
    const int tid  = threadIdx.x;
    const int warp = tid >> 5;
    const int lane = tid & 31;
    const int ql   = warp & 3;        // query 0..3
    const int h    = warp >> 2;       // k-half 0..1
    const float* cb = coor + b * 3 * N_;

    if (blockIdx.x == 0 && b == 0)
        for (int i = tid; i < B_ * NCELL; i += 256) g_cnt[i] = 0;

    if (tid < 128) {
        int qq = tid >> 5, k = tid & 31;
        int id = g_gidx[(b * N_ + q0 + qq) * K_ + k];
        scc[tid] = make_float4((cb[id] - cb[q0 + qq]) * 5.0f,
                               (cb[N_ + id] - cb[N_ + q0 + qq]) * 5.0f,
                               (cb[2 * N_ + id] - cb[2 * N_ + q0 + qq]) * 5.0f,
                               __int_as_float(id));
    }
    __syncthreads();

    const ull wx2 = reinterpret_cast<const ull*>(g_Wc)[lane];
    const ull wy2 = reinterpret_cast<const ull*>(g_Wc + 64)[lane];
    const ull wz2 = reinterpret_cast<const ull*>(g_Wc + 128)[lane];
    const float* Fb = g_F + (size_t)(b * N_) * 64;

    float m0 = __int_as_float(0xff800000), m1 = m0;   // -inf
#pragma unroll
    for (int kk = 0; kk < 16; kk++) {
        float4 cc = scc[ql * 32 + h * 16 + kk];
        int id = __float_as_int(cc.w);
        ull y = reinterpret_cast<const ull*>(Fb + id * 64)[lane];
        FMA2ACC(y, pack2(cc.x, cc.x), wx2);
        FMA2ACC(y, pack2(cc.y, cc.y), wy2);
        FMA2ACC(y, pack2(cc.z, cc.z), wz2);
        float y0, y1; unpack2(y, y0, y1);
        m0 = fmaxf(m0, y0);
        m1 = fmaxf(m1, y1);
    }
    spart[h][ql][2 * lane]     = m0;
    spart[h][ql][2 * lane + 1] = m1;
    __syncthreads();

    {   // combine halves + bias + relu  (max is associative: bit-identical)
        int q2 = tid >> 6, d = tid & 63;
        float m = fmaxf(spart[0][q2][d], spart[1][q2][d]);
        sout[q2 * 64 + d] = fmaxf(m + g_bias[d], 0.f);
    }
    __syncthreads();

    if (tid < 64) {   // transposed store: 4 consecutive n's per d row
        float4 v = make_float4(sout[tid], sout[64 + tid],
                               sout[128 + tid], sout[192 + tid]);
        *reinterpret_cast<float4*>(&out[(b * 64 + tid) * N_ + q0]) = v;
    }
}

// ---------------------------------------------------------------------------
extern "C" void kernel_launch(void* const* d_in, const int* in_sizes, int n_in,
                              void* d_out, int out_size) {
    const float* coor  = (const float*)d_in[0];
    const float* fea   = (const float*)d_in[1];
    const float* W     = (const float*)d_in[2];
    const float* gamma = (const float*)d_in[3];
    const float* beta  = (const float*)d_in[4];
    const float* rmean = (const float*)d_in[5];
    const float* rvar  = (const float*)d_in[6];
    float* out = (float*)d_out;

    k_prep<<<1 + B_ * N_ / 256, 256>>>(coor, W, gamma, beta, rmean, rvar);
    scatter_kernel<<<128, 256>>>(coor);
    fgemm_knn<<<1024 + (N_ / 8) * B_, 256>>>(coor, fea);
    agg_kernel<<<dim3(N_ / 4, B_), 256>>>(coor, out);
}